// round 12
// baseline (speedup 1.0000x reference)
#include <cuda_runtime.h>
#include <cuda_bf16.h>
#include <cstdint>

// LengthRegulator, single launch, SCATTER formulation:
//   x (32,512,384) f32, duration (32,512) int64/int32 (runtime-detected), max_len=4096
//   out = (32,4096,384) f32 + mel_len tail (layout inferred from out_size).
//
// Roles by blockIdx:
//   [0, 32)            producers: scan batch durations -> publish g_csum + mel tail
//   [32, 32+4096)      scatter:   input row i -> store to out rows [csum[i-1], csum[i])
//   [32+4096, ...)     zero-fill: out rows in [mel, 4096) get zeros (early-exit otherwise)
// Scatter has NO dependent load chain: one x-row read, then pure coalesced
// write stream (fire-and-forget stores) -> bound by HBM write bandwidth.

#define B_    32
#define T_    512
#define C_    384
#define ML_   4096
#define C4_   (C_ / 4)             // 96 float4 per row
#define NTHR  384                  // (96, 4)
#define RPS   4                    // input rows per scatter block
#define SPB   (T_ / RPS)           // 128 scatter blocks per batch
#define NSCAT (B_ * SPB)           // 4096
#define RPZ   16                   // output rows per zero block
#define ZPB   (ML_ / RPZ)          // 256 zero blocks per batch
#define NZERO (B_ * ZPB)           // 8192
#define GRID  (B_ + NSCAT + NZERO) // 12320

__device__ int g_csum[B_ * T_];    // inclusive cumsum per batch
__device__ int g_ready;            // producer completion counter (self-resetting)
__device__ unsigned int g_done;    // block completion counter (self-resetting)

__global__ void __launch_bounds__(NTHR) lr_scatter_kernel(const float4* __restrict__ x,
                                                          const void* __restrict__ dur_raw,
                                                          float* __restrict__ out,
                                                          int mel_mode) {
    const int c4  = threadIdx.x;            // 0..95
    const int ty  = threadIdx.y;            // 0..3
    const int tid = ty * C4_ + c4;          // 0..383
    const int bx  = blockIdx.x;

    // ================= PRODUCER: blocks 0..31, one batch each =================
    if (bx < B_) {
        __shared__ int s_csum[T_];
        __shared__ int s_wsum[16];
        const int pb   = bx;
        const int lane = tid & 31;
        const int wid  = tid >> 5;          // 0..11

        // int64 vs int32: odd int32 words of first 512 elements all zero => int64
        int pred = 0;
        for (int i = tid; i < T_; i += NTHR)
            pred |= ((const int*)dur_raw)[2 * i + 1];
        const int is32 = __syncthreads_or(pred != 0);

        for (int i = tid; i < T_; i += NTHR) {
            long long dv;
            if (is32) dv = (long long)((const int*)dur_raw)[(size_t)pb * T_ + i];
            else      dv = ((const long long*)dur_raw)[(size_t)pb * T_ + i];
            s_csum[i] = dv > 0 ? (int)dv : 0;
        }
        __syncthreads();

        // inclusive scan: 16 chunks of 32, warps 0..11 sweep chunks
        for (int chunk = wid; chunk < 16; chunk += 12) {
            int v = s_csum[chunk * 32 + lane];
            #pragma unroll
            for (int off = 1; off < 32; off <<= 1) {
                int n = __shfl_up_sync(0xffffffffu, v, off);
                if (lane >= off) v += n;
            }
            s_csum[chunk * 32 + lane] = v;
            if (lane == 31) s_wsum[chunk] = v;
        }
        __syncthreads();
        if (wid == 0) {
            int wv = (lane < 16) ? s_wsum[lane] : 0;
            #pragma unroll
            for (int off = 1; off < 16; off <<= 1) {
                int n = __shfl_up_sync(0xffffffffu, wv, off);
                if (lane >= off) wv += n;
            }
            if (lane < 16) s_wsum[lane] = wv;
        }
        __syncthreads();

        // publish full cumsum to global
        for (int i = tid; i < T_; i += NTHR) {
            int v = s_csum[i];
            if (i >= 32) v += s_wsum[(i >> 5) - 1];
            g_csum[pb * T_ + i] = v;
            if (i == T_ - 1 && tid < NTHR) {      // mel tail
                const size_t total = (size_t)B_ * ML_ * C_;
                if (mel_mode == 1)      out[total + pb] = (float)v;
                else if (mel_mode == 2) ((long long*)(out + total))[pb] = (long long)v;
            }
        }

        __threadfence();                    // publish before signaling
        __syncthreads();
        if (tid == 0) atomicAdd(&g_ready, 1);
    }

    // ====== PREFETCH (scatter blocks): pull our 4 x rows toward L2 during wait ======
    if (bx >= B_ && bx < B_ + NSCAT && tid < 48) {
        const int sb = bx - B_;
        const int b  = sb / SPB;
        const int i0 = (sb & (SPB - 1)) * RPS;
        const float4* pf = x + ((size_t)b * T_ + i0) * C4_ + tid * 8;
        asm volatile("prefetch.global.L2 [%0];" :: "l"(pf));
    }

    // ================= WAIT: until all 32 producers signaled =================
    if (tid == 0) {
        volatile int* r = &g_ready;
        while (*r < B_) __nanosleep(64);
        __threadfence();                    // acquire
    }
    __syncthreads();

    float4* out4 = (float4*)out;

    if (bx >= B_ && bx < B_ + NSCAT) {
        // ============ SCATTER: 4 input rows, each replicated to its out range ============
        const int sb = bx - B_;
        const int b  = sb / SPB;
        const int i  = (sb & (SPB - 1)) * RPS + ty;    // this ty's input row

        int start = (i == 0) ? 0 : g_csum[b * T_ + i - 1];
        int end   = g_csum[b * T_ + i];
        if (end > ML_)   end = ML_;
        if (start > ML_) start = ML_;

        if (start < end) {
            const float4 v = __ldg(&x[((size_t)b * T_ + i) * C4_ + c4]);
            float4* ob = out4 + (size_t)b * ML_ * C4_;
            for (int p = start; p < end; ++p)
                __stcs(&ob[(size_t)p * C4_ + c4], v);   // coalesced, fire-and-forget
        }
    } else if (bx >= B_ + NSCAT) {
        // ============ ZERO-FILL: rows in [mel, ML_) ============
        const int zb = bx - B_ - NSCAT;
        const int b  = zb / ZPB;
        const int p0 = (zb & (ZPB - 1)) * RPZ;

        int mel = g_csum[b * T_ + T_ - 1];
        if (mel > ML_) mel = ML_;

        if (p0 + RPZ > mel) {
            const float4 z = make_float4(0.f, 0.f, 0.f, 0.f);
            float4* ob = out4 + (size_t)b * ML_ * C4_;
            #pragma unroll
            for (int k = 0; k < RPZ / 4; ++k) {
                int p = p0 + ty + 4 * k;
                if (p >= mel)
                    __stcs(&ob[(size_t)p * C4_ + c4], z);
            }
        }
    }

    // ================= RESET flags (last block) for deterministic replay =======
    __syncthreads();
    if (tid == 0) {
        if (atomicAdd(&g_done, 1u) == (unsigned)(GRID - 1)) {
            g_done  = 0u;
            g_ready = 0;
        }
    }
}

// ---------------------------------------------------------------------------
extern "C" void kernel_launch(void* const* d_in, const int* in_sizes, int n_in,
                              void* d_out, int out_size) {
    const float* x   = (const float*)d_in[0];
    const void*  dur = d_in[1];
    float* out = (float*)d_out;

    const long long total = (long long)B_ * ML_ * C_;
    const long long extra = (long long)out_size - total;
    int mel_mode = 0;
    if (extra == B_)          mel_mode = 1;   // float32 tail
    else if (extra == 2 * B_) mel_mode = 2;   // raw int64 tail

    dim3 blk(C4_, 4);
    lr_scatter_kernel<<<GRID, blk>>>((const float4*)x, dur, out, mel_mode);
}

// round 13
// speedup vs baseline: 1.1140x; 1.1140x over previous
#include <cuda_runtime.h>
#include <cuda_bf16.h>
#include <cstdint>

// LengthRegulator, two-kernel:
//   x (32,512,384) f32, duration (32,512) int64/int32 (runtime-detected), max_len=4096
//   out = (32,4096,384) f32 + mel_len tail (layout inferred from out_size).
//
// K1 (256 blocks, 8/batch): redundant per-block shuffle scan of the batch's 512
//     durations, then inverse-scatter of a 512-position slice of g_idx. ~1.5us.
// K2 (8192 blocks): proven LTS-cap expand body (35.8us): 16 rows/block, UNR=4,
//     warp-uniform idx loads, fully coalesced float4 stores.

#define B_   32
#define T_   512
#define C_   384
#define ML_  4096
#define C4_  (C_ / 4)            // 96 float4 per row
#define RPB  16                  // rows per expand block
#define UNR  4                   // rows per thread
#define NTHR (C4_ * 4)           // 384 threads (expand)
#define SPB  8                   // scan blocks per batch
#define SLC  (ML_ / SPB)         // 512 output positions per scan block

__device__ int g_idx[B_ * ML_];  // input-row index per output row; -1 = masked

// ---------------------------------------------------------------------------
// Kernel 1: grid = B_*SPB = 256, block = T_ (512 threads).
// Each block: scan batch durations, inverse-scatter its g_idx slice.
// ---------------------------------------------------------------------------
__global__ void __launch_bounds__(T_) lr_scan_kernel(const void* __restrict__ dur_raw,
                                                     float* __restrict__ out,
                                                     int mel_mode) {
    __shared__ int s_csum[T_];
    __shared__ int s_wsum[16];

    const int t    = threadIdx.x;
    const int b    = blockIdx.x >> 3;           // batch
    const int s    = blockIdx.x & (SPB - 1);    // slice within batch
    const int lane = t & 31;
    const int wid  = t >> 5;

    // int64 vs int32: odd int32 words of first 512 elements all zero => int64
    int pred = ((const int*)dur_raw)[2 * t + 1];
    const int is32 = __syncthreads_or(pred != 0);

    long long dv;
    if (is32) dv = (long long)((const int*)dur_raw)[(size_t)b * T_ + t];
    else      dv = ((const long long*)dur_raw)[(size_t)b * T_ + t];
    int v = dv > 0 ? (int)dv : 0;

    // warp inclusive scan
    #pragma unroll
    for (int off = 1; off < 32; off <<= 1) {
        int n = __shfl_up_sync(0xffffffffu, v, off);
        if (lane >= off) v += n;
    }
    if (lane == 31) s_wsum[wid] = v;
    __syncthreads();
    if (wid == 0) {
        int wv = (lane < 16) ? s_wsum[lane] : 0;
        #pragma unroll
        for (int off = 1; off < 16; off <<= 1) {
            int n = __shfl_up_sync(0xffffffffu, wv, off);
            if (lane >= off) wv += n;
        }
        if (lane < 16) s_wsum[lane] = wv;
    }
    __syncthreads();
    if (wid > 0) v += s_wsum[wid - 1];
    s_csum[t] = v;
    __syncthreads();

    const int mel = s_csum[T_ - 1];

    // mel tail (one block per batch)
    if (s == 0 && t == 0) {
        const size_t total = (size_t)B_ * ML_ * C_;
        if (mel_mode == 1)      out[total + b] = (float)mel;
        else if (mel_mode == 2) ((long long*)(out + total))[b] = (long long)mel;
    }

    // inverse scatter restricted to this block's slice [p0, p1)
    const int p0 = s * SLC;
    const int p1 = p0 + SLC;
    int* gb = g_idx + b * ML_;

    {   // thread t owns input row t: fill [csum[t-1], csum[t]) ∩ [p0, p1)
        int start = (t == 0) ? 0 : s_csum[t - 1];
        int end   = s_csum[t];
        if (start < p0) start = p0;
        if (end   > p1) end   = p1;
        for (int p = start; p < end; ++p) gb[p] = t;
    }
    {   // masked tail within slice: [max(mel,p0), p1)
        int mstart = mel > p0 ? mel : p0;
        for (int p = mstart + t; p < p1; p += T_) gb[p] = -1;
    }
}

// ---------------------------------------------------------------------------
// Kernel 2: proven expand body. grid = B_*ML_/RPB = 8192, block (96,4).
// ---------------------------------------------------------------------------
__global__ void __launch_bounds__(NTHR) lr_expand_kernel(const float4* __restrict__ x,
                                                         float4* __restrict__ out) {
    const int c4      = threadIdx.x;                   // 0..95
    const int ty      = threadIdx.y;                   // 0..3
    const int rowBase = blockIdx.x * RPB + ty;         // rows: rowBase + 4*k
    const int b       = (blockIdx.x * RPB) >> 12;      // batch (RPB | ML_)

    int idx[UNR];
    #pragma unroll
    for (int k = 0; k < UNR; ++k)
        idx[k] = g_idx[rowBase + 4 * k];               // warp-uniform

    const float4* xb = x + (size_t)b * T_ * C4_;
    float4 v[UNR];
    #pragma unroll
    for (int k = 0; k < UNR; ++k) {
        if (idx[k] >= 0) v[k] = __ldg(&xb[(size_t)idx[k] * C4_ + c4]);
        else             v[k] = make_float4(0.f, 0.f, 0.f, 0.f);
    }

    #pragma unroll
    for (int k = 0; k < UNR; ++k)
        out[(size_t)(rowBase + 4 * k) * C4_ + c4] = v[k];   // coalesced 1536 B/row
}

// ---------------------------------------------------------------------------
extern "C" void kernel_launch(void* const* d_in, const int* in_sizes, int n_in,
                              void* d_out, int out_size) {
    const float* x   = (const float*)d_in[0];
    const void*  dur = d_in[1];
    float* out = (float*)d_out;

    const long long total = (long long)B_ * ML_ * C_;
    const long long extra = (long long)out_size - total;
    int mel_mode = 0;
    if (extra == B_)          mel_mode = 1;   // float32 tail
    else if (extra == 2 * B_) mel_mode = 2;   // raw int64 tail

    lr_scan_kernel<<<B_ * SPB, T_>>>(dur, out, mel_mode);

    dim3 blk(C4_, 4);
    lr_expand_kernel<<<(B_ * ML_) / RPB, blk>>>((const float4*)x, (float4*)out);
}